// round 15
// baseline (speedup 1.0000x reference)
#include <cuda_runtime.h>

// LengthRegulator: out[b,t,:] = x[b, tok(b,t), :] where tok = searchsorted(cumsum(dur), t, 'right')
// Static shapes: B=16, L=512, D=512, T_MAX=4096. Output fp32 [B, T, D].
//
// FUSED single kernel, 512 threads / 32 frames per block:
//  - one redundant per-block scan of the batch's 512 durations (4x less scan work
//    than the 256-thread version),
//  - each warp resolves 2 consecutive frames (parallel half-warp binary searches),
//  - R6-style fully-coalesced warp-strided gather, 8 loads in flight per thread.

constexpr int B = 16;
constexpr int L = 512;
constexpr int D = 512;          // 512 floats = 128 float4 per row
constexpr int T = 4096;
constexpr int D4 = D / 4;       // 128 float4 per row
constexpr int FPB = 32;         // frames per block

__global__ void __launch_bounds__(512) fused_kernel(
    const int*    __restrict__ dur,
    const float4* __restrict__ x4,
    float4*       __restrict__ out4)
{
    __shared__ int s[L];          // inclusive cumsum of durations for this batch
    __shared__ int wsum[16];      // per-warp scan totals

    const int tid  = threadIdx.x;        // 0..511
    const int lane = tid & 31;
    const int wrp  = tid >> 5;           // 0..15
    const int frb  = blockIdx.x * FPB;   // first of 32 consecutive frames (32 | T -> b uniform)
    const int b    = frb >> 12;          // batch

    // ---- per-block scan of dur[b, 0..511] (1 int per thread) ----
    int v = dur[b * L + tid];
    #pragma unroll
    for (int off = 1; off < 32; off <<= 1) {
        int n = __shfl_up_sync(0xffffffffu, v, off);
        if (lane >= off) v += n;
    }
    if (lane == 31) wsum[wrp] = v;
    __syncthreads();

    if (wrp == 0 && lane < 16) {
        int p = wsum[lane];
        #pragma unroll
        for (int off = 1; off < 16; off <<= 1) {
            int n = __shfl_up_sync(0x0000ffffu, p, off);
            if (lane >= off) p += n;
        }
        wsum[lane] = p;
    }
    __syncthreads();

    const int base = (wrp > 0) ? wsum[wrp - 1] : 0;
    s[tid] = v + base;
    __syncthreads();

    const int total = s[L - 1];

    // ---- 2 frames per warp; half-warp parallel upper_bound searches ----
    const int fr0 = frb + wrp * 2;             // warp's first frame
    const int fr  = fr0 + (lane >> 4);         // lanes 0-15: fr0, lanes 16-31: fr0+1
    const int t   = fr & (T - 1);

    int tok;
    if (t >= total) {
        tok = -1;
    } else {
        int lo = 0, hi = L;
        while (lo < hi) {
            int mid = (lo + hi) >> 1;
            if (s[mid] <= t) lo = mid + 1; else hi = mid;
        }
        tok = lo < (L - 1) ? lo : (L - 1);
    }
    const int tok0 = __shfl_sync(0xffffffffu, tok, 0);
    const int tok1 = __shfl_sync(0xffffffffu, tok, 16);

    // ---- gather: 4 warp-strided float4 per thread per frame, fully coalesced ----
    const float4* xb   = x4 + (b * L) * D4 + lane;
    float4*       dst0 = out4 + fr0 * D4 + lane;
    float4*       dst1 = dst0 + D4;

    if (tok0 >= 0 && tok1 >= 0) {
        // common path: 8 independent loads in flight, then 8 streaming stores
        const float4* s0 = xb + tok0 * D4;
        const float4* s1 = xb + tok1 * D4;
        float4 a0 = __ldg(s0 +  0);
        float4 a1 = __ldg(s0 + 32);
        float4 a2 = __ldg(s0 + 64);
        float4 a3 = __ldg(s0 + 96);
        float4 c0 = __ldg(s1 +  0);
        float4 c1 = __ldg(s1 + 32);
        float4 c2 = __ldg(s1 + 64);
        float4 c3 = __ldg(s1 + 96);
        __stcs(dst0 +  0, a0);
        __stcs(dst0 + 32, a1);
        __stcs(dst0 + 64, a2);
        __stcs(dst0 + 96, a3);
        __stcs(dst1 +  0, c0);
        __stcs(dst1 + 32, c1);
        __stcs(dst1 + 64, c2);
        __stcs(dst1 + 96, c3);
    } else {
        const float4 z = make_float4(0.f, 0.f, 0.f, 0.f);
        if (tok0 >= 0) {
            const float4* s0 = xb + tok0 * D4;
            float4 a0 = __ldg(s0 +  0);
            float4 a1 = __ldg(s0 + 32);
            float4 a2 = __ldg(s0 + 64);
            float4 a3 = __ldg(s0 + 96);
            __stcs(dst0 +  0, a0);
            __stcs(dst0 + 32, a1);
            __stcs(dst0 + 64, a2);
            __stcs(dst0 + 96, a3);
        } else {
            __stcs(dst0 +  0, z);
            __stcs(dst0 + 32, z);
            __stcs(dst0 + 64, z);
            __stcs(dst0 + 96, z);
        }
        if (tok1 >= 0) {
            const float4* s1 = xb + tok1 * D4;
            float4 c0 = __ldg(s1 +  0);
            float4 c1 = __ldg(s1 + 32);
            float4 c2 = __ldg(s1 + 64);
            float4 c3 = __ldg(s1 + 96);
            __stcs(dst1 +  0, c0);
            __stcs(dst1 + 32, c1);
            __stcs(dst1 + 64, c2);
            __stcs(dst1 + 96, c3);
        } else {
            __stcs(dst1 +  0, z);
            __stcs(dst1 + 32, z);
            __stcs(dst1 + 64, z);
            __stcs(dst1 + 96, z);
        }
    }
}

extern "C" void kernel_launch(void* const* d_in, const int* in_sizes, int n_in,
                              void* d_out, int out_size) {
    const float* x   = (const float*)d_in[0];
    const int*   dur = (const int*)d_in[1];
    // d_in[2] = mel_max_length (static 4096, baked into constants)

    const int blocks = (B * T) / FPB;    // 2048 blocks, 32 frames each
    fused_kernel<<<blocks, 512>>>(dur, (const float4*)x, (float4*)d_out);

    (void)in_sizes; (void)n_in; (void)out_size;
}